// round 4
// baseline (speedup 1.0000x reference)
#include <cuda_runtime.h>

#define Tn 512
#define Bn 64
#define Vn 256
#define Hn 512
#define NPAIR 4
#define GRID_SCAN 128
#define NTHR 256

// ---------------- device scratch (no allocations allowed) ----------------
__device__ float g_embhg[Vn * 2 * Hn];                 // emb @ w_in[0] : [256][1024]
__device__ float g_state[2][2][Bn * Hn];               // [layer][parity][B*H]
__device__ float g_hidden[(size_t)Tn * Bn * Hn];       // per-step layer-1 output, 64MB
__device__ unsigned g_bar_count;
__device__ unsigned g_bar_gen;

// ---------------- grid-wide barrier (sense reversal, stateless across replays) ----
__device__ __forceinline__ void grid_sync() {
  __syncthreads();
  if (threadIdx.x == 0) {
    volatile unsigned* genp = (volatile unsigned*)&g_bar_gen;
    unsigned gen = *genp;
    __threadfence();
    if (atomicAdd(&g_bar_count, 1u) == GRID_SCAN - 1u) {
      g_bar_count = 0u;
      __threadfence();
      atomicAdd(&g_bar_gen, 1u);
    } else {
      while (*genp == gen) { __nanosleep(20); }
    }
    __threadfence();
  }
  __syncthreads();
}

// ---------------- K=512 dual dot-product pass ----------------
// acc.x += src[b,:] . wh[:],  acc.y += src[b,:] . wg[:]
// src is a [64][512] fp32 state buffer in global (read via .cg, L1 is stale-unsafe
// for cross-CTA data within a launch). Weights come from SMEM (resident all run).
// s is staged in double-buffered SMEM chunks of 64 k (padded rows, conflict-free
// LDS.128), prefetched one chunk ahead so L2 latency overlaps FFMA.
__device__ __noinline__ float2 kpass(float2 acc,
    const float* __restrict__ src,
    const float* __restrict__ wh, const float* __restrict__ wg,
    float* __restrict__ s_sm, int tid, int b)
{
  const int PAD = 68;  // 64 + 4 pad -> bank-conflict-free LDS.128, 16B aligned rows
  float4 ld[4];
#pragma unroll
  for (int i = 0; i < 4; ++i) {
    int e = tid + i * NTHR;
    int lb = e >> 4, lk = (e & 15) << 2;
    ld[i] = __ldcg((const float4*)(src + lb * 512 + lk));
  }
  float ah = acc.x, ag = acc.y;
#pragma unroll 1
  for (int c = 0; c < 8; ++c) {
    float* buf = s_sm + (c & 1) * (64 * PAD);
#pragma unroll
    for (int i = 0; i < 4; ++i) {
      int e = tid + i * NTHR;
      int lb = e >> 4, lk = (e & 15) << 2;
      *(float4*)(buf + lb * PAD + lk) = ld[i];
    }
    __syncthreads();   // single sync/chunk: program order covers WAR on buffers
    if (c < 7) {
#pragma unroll
      for (int i = 0; i < 4; ++i) {
        int e = tid + i * NTHR;
        int lb = e >> 4, lk = (e & 15) << 2;
        ld[i] = __ldcg((const float4*)(src + lb * 512 + (c + 1) * 64 + lk));
      }
    }
    const float* srow = buf + b * PAD;
    const float* whc = wh + c * 64;
    const float* wgc = wg + c * 64;
#pragma unroll
    for (int kk = 0; kk < 64; kk += 4) {
      float4 sv = *(const float4*)(srow + kk);
      float4 h4 = *(const float4*)(whc + kk);
      float4 g4 = *(const float4*)(wgc + kk);
      ah = fmaf(sv.x, h4.x, ah); ah = fmaf(sv.y, h4.y, ah);
      ah = fmaf(sv.z, h4.z, ah); ah = fmaf(sv.w, h4.w, ah);
      ag = fmaf(sv.x, g4.x, ag); ag = fmaf(sv.y, g4.y, ag);
      ag = fmaf(sv.z, g4.z, ag); ag = fmaf(sv.w, g4.w, ag);
    }
  }
  return make_float2(ah, ag);
}

// ---------------- kernel 1: embhg = emb @ w_in[0]  ([256,512]@[512,1024]) -------
__global__ void embhg_kernel(const float* __restrict__ emb,
                             const float* __restrict__ w_in) {
  __shared__ float e_sm[512];
  int v = blockIdx.x;
  for (int i = threadIdx.x; i < 512; i += NTHR) e_sm[i] = emb[v * 512 + i];
  __syncthreads();
  for (int j = threadIdx.x; j < 1024; j += NTHR) {
    float a0 = 0.f, a1 = 0.f, a2 = 0.f, a3 = 0.f;
    for (int k = 0; k < 512; k += 4) {
      a0 = fmaf(e_sm[k + 0], w_in[(size_t)(k + 0) * 1024 + j], a0);
      a1 = fmaf(e_sm[k + 1], w_in[(size_t)(k + 1) * 1024 + j], a1);
      a2 = fmaf(e_sm[k + 2], w_in[(size_t)(k + 2) * 1024 + j], a2);
      a3 = fmaf(e_sm[k + 3], w_in[(size_t)(k + 3) * 1024 + j], a3);
    }
    g_embhg[v * 1024 + j] = (a0 + a1) + (a2 + a3);
  }
}

// ---------------- kernel 2: persistent sequential scan ----------------
// SMEM layout per CTA:
//   ws [9][4][2][512]  : column-pair slices of the 9 matrices
//                        m=0..3 -> w_h[0][d]; m=4 -> w_in[1]; m=5..8 -> w_h[1][d]
//   bs [9][4][2]       : bias slices (m=4 zero)
//   s_sm [2][64*68]    : double-buffered s staging
//   tok [64]           : tokens of the current timestep
__global__ void __launch_bounds__(NTHR, 1) scan_kernel(
    const int* __restrict__ x, const float* __restrict__ w_in,
    const float* __restrict__ w_h, const float* __restrict__ b_h,
    float* __restrict__ d_out)
{
  extern __shared__ float smem[];
  float* ws = smem;                          // 36864 floats
  float* bs = ws + 9 * NPAIR * 2 * 512;      // 72 floats
  float* s_sm = bs + 72;                     // 8704 floats (16B aligned)
  int* tok = (int*)(s_sm + 2 * 64 * 68);

  int tid = threadIdx.x;
  int cta = blockIdx.x;

  // --- load this CTA's weight slices into SMEM (one time per launch) ---
  for (int idx = tid; idx < 9 * 4096; idx += NTHR) {
    int m = idx >> 12;
    int e = idx & 4095;
    int k = e >> 3;
    int c = e & 7;
    int p = c & 3, hg = c >> 2;
    int col = cta * NPAIR + p + hg * 512;
    const float* W = (m < 4)  ? (w_h + (size_t)m * 512 * 1024)
                   : (m == 4) ? (w_in + (size_t)512 * 1024)
                              : (w_h + (size_t)(m - 1) * 512 * 1024);
    ws[(((m * NPAIR) + p) * 2 + hg) * 512 + k] = W[(size_t)k * 1024 + col];
  }
  if (tid < 72) {
    int m = tid >> 3, pp = (tid >> 1) & 3, hg = tid & 1;
    int col = cta * NPAIR + pp + hg * 512;
    float v = 0.f;
    if (m < 4)      v = b_h[m * 1024 + col];
    else if (m > 4) v = b_h[(m - 1) * 1024 + col];
    bs[tid] = v;
  }
  // --- zero the state buffers ---
  for (int i = cta * NTHR + tid; i < 2 * 2 * Bn * Hn; i += GRID_SCAN * NTHR)
    ((float*)g_state)[i] = 0.f;
  grid_sync();

  int b = tid & 63;           // batch row
  int p = tid >> 6;           // local pair 0..3
  int pairc = cta * NPAIR + p;  // global pair/state column 0..511
  int par0 = 0, par1 = 0;

#pragma unroll 1
  for (int t = 0; t < Tn; ++t) {
    if (tid < 64) tok[tid] = x[t * Bn + tid];
    __syncthreads();
    int tkn = tok[b];

    // ---- layer 0, depth 0..3 ----
#pragma unroll 1
    for (int d = 0; d < 4; ++d) {
      const float* wm = ws + ((d * NPAIR + p) * 2) * 512;
      const float* src = g_state[0][par0];
      float2 acc;
      acc.x = bs[(d * NPAIR + p) * 2 + 0];
      acc.y = bs[(d * NPAIR + p) * 2 + 1];
      float s_old = __ldcg(src + b * 512 + pairc);
      if (d == 0) {
        acc.x += g_embhg[tkn * 1024 + pairc];
        acc.y += g_embhg[tkn * 1024 + 512 + pairc];
      }
      acc = kpass(acc, src, wm, wm + 512, s_sm, tid, b);
      float hh = tanhf(acc.x);
      float gg = 1.f / (1.f + __expf(-acc.y));
      float s_new = fmaf(gg, hh - s_old, s_old);
      __stcg(g_state[0][par0 ^ 1] + b * 512 + pairc, s_new);
      par0 ^= 1;
      grid_sync();
    }

    // ---- layer 1, depth 0..3 (d0 fuses the w_in[1] input projection) ----
#pragma unroll 1
    for (int d = 0; d < 4; ++d) {
      int m = 5 + d;
      const float* wm = ws + ((m * NPAIR + p) * 2) * 512;
      const float* src = g_state[1][par1];
      float2 acc;
      acc.x = bs[(m * NPAIR + p) * 2 + 0];
      acc.y = bs[(m * NPAIR + p) * 2 + 1];
      float s_old = __ldcg(src + b * 512 + pairc);
      acc = kpass(acc, src, wm, wm + 512, s_sm, tid, b);
      if (d == 0) {
        const float* wi = ws + ((4 * NPAIR + p) * 2) * 512;
        acc = kpass(acc, g_state[0][par0], wi, wi + 512, s_sm, tid, b);
      }
      float hh = tanhf(acc.x);
      float gg = 1.f / (1.f + __expf(-acc.y));
      float s_new = fmaf(gg, hh - s_old, s_old);
      __stcg(g_state[1][par1 ^ 1] + b * 512 + pairc, s_new);
      par1 ^= 1;
      if (d == 3) g_hidden[(size_t)t * (Bn * Hn) + b * 512 + pairc] = s_new;
      grid_sync();
    }
  }

  // ---- s_final: [L][B][H] appended after the logits block ----
  const size_t SFIN = (size_t)Tn * Bn * Vn;  // 8388608
  d_out[SFIN + 0 * (Bn * Hn) + b * 512 + pairc] =
      __ldcg(g_state[0][par0] + b * 512 + pairc);
  d_out[SFIN + 1 * (Bn * Hn) + b * 512 + pairc] =
      __ldcg(g_state[1][par1] + b * 512 + pairc);
}

// ---------------- kernel 3: logits = hidden @ w_fc + b_fc ----------------
// [32768, 512] @ [512, 256]. Each CTA: 64 rows x 256 cols; A-tile in SMEM,
// per-thread 64 accumulators (one column per thread), FFMA-bound.
__global__ void __launch_bounds__(NTHR, 1) logits_kernel(
    const float* __restrict__ w_fc, const float* __restrict__ b_fc,
    float* __restrict__ out)
{
  extern __shared__ float a_sm[];  // [64][512]
  int tid = threadIdx.x;
  size_t row0 = (size_t)blockIdx.x * 64;
  for (int i = tid; i < 64 * 512 / 4; i += NTHR)
    ((float4*)a_sm)[i] = ((const float4*)(g_hidden + row0 * 512))[i];
  __syncthreads();

  float acc[64];
#pragma unroll
  for (int r = 0; r < 64; ++r) acc[r] = 0.f;

#pragma unroll 2
  for (int k = 0; k < 512; k += 4) {
    float w0 = w_fc[(size_t)(k + 0) * 256 + tid];
    float w1 = w_fc[(size_t)(k + 1) * 256 + tid];
    float w2 = w_fc[(size_t)(k + 2) * 256 + tid];
    float w3 = w_fc[(size_t)(k + 3) * 256 + tid];
#pragma unroll
    for (int r = 0; r < 64; ++r) {
      float4 a = *(const float4*)(a_sm + r * 512 + k);
      acc[r] = fmaf(a.x, w0, acc[r]);
      acc[r] = fmaf(a.y, w1, acc[r]);
      acc[r] = fmaf(a.z, w2, acc[r]);
      acc[r] = fmaf(a.w, w3, acc[r]);
    }
  }
  float bias = b_fc[tid];
#pragma unroll
  for (int r = 0; r < 64; ++r)
    out[(row0 + r) * 256 + tid] = acc[r] + bias;
}

// ---------------- launch ----------------
extern "C" void kernel_launch(void* const* d_in, const int* in_sizes, int n_in,
                              void* d_out, int out_size) {
  const int*   x    = (const int*)d_in[0];    // [512,64] int32
  const float* emb  = (const float*)d_in[1];  // [256,512]
  const float* w_in = (const float*)d_in[2];  // [2,512,1024]
  const float* w_h  = (const float*)d_in[3];  // [2,4,512,1024]
  const float* b_h  = (const float*)d_in[4];  // [2,4,1024]
  const float* w_fc = (const float*)d_in[5];  // [512,256]
  const float* b_fc = (const float*)d_in[6];  // [256]
  float* out = (float*)d_out;

  const int SCAN_SMEM = (9 * NPAIR * 2 * 512 + 72 + 2 * 64 * 68) * 4 + 64 * 4;
  const int LOGITS_SMEM = 64 * 512 * 4;
  cudaFuncSetAttribute(scan_kernel,
                       cudaFuncAttributeMaxDynamicSharedMemorySize, SCAN_SMEM);
  cudaFuncSetAttribute(logits_kernel,
                       cudaFuncAttributeMaxDynamicSharedMemorySize, LOGITS_SMEM);

  embhg_kernel<<<Vn, NTHR>>>(emb, w_in);
  scan_kernel<<<GRID_SCAN, NTHR, SCAN_SMEM>>>(x, w_in, w_h, b_h, out);
  logits_kernel<<<(Tn * Bn) / 64, NTHR, LOGITS_SMEM>>>(w_fc, b_fc, out);
}

// round 5
// speedup vs baseline: 1.9098x; 1.9098x over previous
#include <cuda_runtime.h>

#define Tn 512
#define Bn 64
#define Vn 256
#define Hn 512
#define GRID_SCAN 128
#define NTHR 256

// ---------------- device scratch (no allocations allowed) ----------------
__device__ float g_embhg[Vn * 2 * Hn];                 // emb @ w_in[0] : [256][1024]
__device__ float g_state[2][2][Hn * Bn];               // [layer][parity][col*64 + b]
__device__ float g_hidden[(size_t)Tn * Bn * Hn];       // [t][b][col]
__device__ unsigned g_bar_count;
__device__ unsigned g_bar_gen;

// ---------------- grid-wide barrier (sense reversal) ----------------
__device__ __forceinline__ void grid_sync() {
  __syncthreads();
  if (threadIdx.x == 0) {
    volatile unsigned* genp = (volatile unsigned*)&g_bar_gen;
    unsigned gen = *genp;
    __threadfence();
    if (atomicAdd(&g_bar_count, 1u) == GRID_SCAN - 1u) {
      g_bar_count = 0u;
      __threadfence();
      atomicAdd(&g_bar_gen, 1u);
    } else {
      while (*genp == gen) { }
    }
    __threadfence();
  }
  __syncthreads();
}

// 32 FMA on one (k, s4) step: 4 batches x 8 cols
#define FMA8(bi, sv)                                                        \
  acc[bi][0] = fmaf(sv, wa.x, acc[bi][0]);                                  \
  acc[bi][1] = fmaf(sv, wa.y, acc[bi][1]);                                  \
  acc[bi][2] = fmaf(sv, wa.z, acc[bi][2]);                                  \
  acc[bi][3] = fmaf(sv, wa.w, acc[bi][3]);                                  \
  acc[bi][4] = fmaf(sv, wb.x, acc[bi][4]);                                  \
  acc[bi][5] = fmaf(sv, wb.y, acc[bi][5]);                                  \
  acc[bi][6] = fmaf(sv, wb.z, acc[bi][6]);                                  \
  acc[bi][7] = fmaf(sv, wb.w, acc[bi][7]);

// ---------------- K=512 partial dual-GEMM pass ----------------
// Thread (ks, bg): accumulates acc[b'][c] += s[k][4bg+b'] * w[k][c]
// over its 32 k values (k = ks + 16*i). s is read straight from L2 with
// coalesced LDG.128 (each 16B of s touched by exactly one thread/CTA);
// weights come from resident SMEM [k][8] rows (broadcast, conflict-free).
__device__ __forceinline__ void kpass(float acc[4][8],
    const float* __restrict__ src, const float* __restrict__ wmat,
    int ks, int bg)
{
  const float4* srcv = (const float4*)src;   // [512][16] float4
  float4 sb[2][8];
#pragma unroll
  for (int j = 0; j < 8; ++j)
    sb[0][j] = __ldcg(srcv + (ks + 16 * j) * 16 + bg);
#pragma unroll
  for (int g = 0; g < 4; ++g) {
    if (g < 3) {
#pragma unroll
      for (int j = 0; j < 8; ++j)
        sb[(g + 1) & 1][j] =
            __ldcg(srcv + (ks + 16 * (8 * (g + 1) + j)) * 16 + bg);
    }
#pragma unroll
    for (int j = 0; j < 8; ++j) {
      int k = ks + 16 * (8 * g + j);
      const float4* wr = (const float4*)(wmat + k * 8);
      float4 wa = wr[0];
      float4 wb = wr[1];
      float4 s4 = sb[g & 1][j];
      FMA8(0, s4.x)
      FMA8(1, s4.y)
      FMA8(2, s4.z)
      FMA8(3, s4.w)
    }
  }
}

// ---------------- kernel 1: embhg = emb @ w_in[0] ----------------
__global__ void embhg_kernel(const float* __restrict__ emb,
                             const float* __restrict__ w_in) {
  __shared__ float e_sm[512];
  int v = blockIdx.x;
  for (int i = threadIdx.x; i < 512; i += NTHR) e_sm[i] = emb[v * 512 + i];
  __syncthreads();
  for (int j = threadIdx.x; j < 1024; j += NTHR) {
    float a0 = 0.f, a1 = 0.f, a2 = 0.f, a3 = 0.f;
    for (int k = 0; k < 512; k += 4) {
      a0 = fmaf(e_sm[k + 0], w_in[(size_t)(k + 0) * 1024 + j], a0);
      a1 = fmaf(e_sm[k + 1], w_in[(size_t)(k + 1) * 1024 + j], a1);
      a2 = fmaf(e_sm[k + 2], w_in[(size_t)(k + 2) * 1024 + j], a2);
      a3 = fmaf(e_sm[k + 3], w_in[(size_t)(k + 3) * 1024 + j], a3);
    }
    g_embhg[v * 1024 + j] = (a0 + a1) + (a2 + a3);
  }
}

// ---------------- kernel 2: persistent sequential scan ----------------
// SMEM: ws [9][512][8] weight rows ([h0..h3,g0..g3] per k), bs [9][8] biases,
//       red [256][36] k-partial buffer (stride 36 = conflict-free STS.128),
//       tok [64].
__global__ void __launch_bounds__(NTHR, 1) scan_kernel(
    const int* __restrict__ x, const float* __restrict__ w_in,
    const float* __restrict__ w_h, const float* __restrict__ b_h,
    float* __restrict__ d_out)
{
  extern __shared__ float smem[];
  float* ws = smem;                 // 9*4096 = 36864 floats
  float* bs = ws + 9 * 4096;        // 72 floats
  float* red = bs + 72;             // 256*36 = 9216 floats
  int* tok = (int*)(red + 256 * 36);

  int tid = threadIdx.x;
  int cta = blockIdx.x;

  // --- weight slices -> SMEM, layout [m][k][8]: cols h0..h3,g0..g3 ---
  for (int idx = tid; idx < 9 * 4096; idx += NTHR) {
    int m = idx >> 12;
    int r = idx & 4095;
    int k = r >> 3;
    int c = r & 7;
    int col = cta * 4 + (c & 3) + ((c >> 2) << 9);
    const float* W = (m < 4)  ? (w_h + (size_t)m * 512 * 1024)
                   : (m == 4) ? (w_in + (size_t)512 * 1024)
                              : (w_h + (size_t)(m - 1) * 512 * 1024);
    ws[idx] = W[(size_t)k * 1024 + col];
  }
  if (tid < 72) {
    int m = tid >> 3, c = tid & 7;
    int col = cta * 4 + (c & 3) + ((c >> 2) << 9);
    float v = 0.f;
    if (m < 4)      v = b_h[m * 1024 + col];
    else if (m > 4) v = b_h[(m - 1) * 1024 + col];
    bs[tid] = v;
  }
  // --- zero state buffers ---
  for (int i = cta * NTHR + tid; i < 2 * 2 * Hn * Bn; i += GRID_SCAN * NTHR)
    ((float*)g_state)[i] = 0.f;
  grid_sync();

  const int ks = tid >> 4;      // k-slice 0..15
  const int bg = tid & 15;      // batch group (4 batches)
  const int p  = tid >> 6;      // combine role: pair 0..3
  const int bq = tid & 63;      // combine role: batch 0..63
  const int gcol = cta * 4 + p; // global h-column of this pair
  float* myred = red + tid * 36;
  int par0 = 0, par1 = 0;

#pragma unroll 1
  for (int t = 0; t < Tn; ++t) {
    if (tid < 64) tok[tid] = x[t * Bn + tid];   // covered by the STS->sync below

    // ---- layer 0, depth 0..3 ----
#pragma unroll 1
    for (int d = 0; d < 4; ++d) {
      float acc[4][8];
#pragma unroll
      for (int a = 0; a < 4; ++a)
#pragma unroll
        for (int c = 0; c < 8; ++c) acc[a][c] = 0.f;

      kpass(acc, g_state[0][par0], ws + d * 4096, ks, bg);

#pragma unroll
      for (int a = 0; a < 4; ++a) {
        *(float4*)(myred + a * 8) =
            make_float4(acc[a][0], acc[a][1], acc[a][2], acc[a][3]);
        *(float4*)(myred + a * 8 + 4) =
            make_float4(acc[a][4], acc[a][5], acc[a][6], acc[a][7]);
      }
      __syncthreads();

      float hs = bs[d * 8 + p];
      float gs = bs[d * 8 + 4 + p];
#pragma unroll
      for (int k2 = 0; k2 < 16; ++k2) {
        const float* rr = red + (k2 * 16 + (bq >> 2)) * 36 + (bq & 3) * 8;
        hs += rr[p];
        gs += rr[4 + p];
      }
      if (d == 0) {
        int tk = tok[bq];
        hs += g_embhg[tk * 1024 + gcol];
        gs += g_embhg[tk * 1024 + 512 + gcol];
      }
      float s_old = __ldcg(g_state[0][par0] + gcol * 64 + bq);
      float hh = tanhf(hs);
      float gg = 1.f / (1.f + __expf(-gs));
      float s_new = fmaf(gg, hh - s_old, s_old);
      __stcg(g_state[0][par0 ^ 1] + gcol * 64 + bq, s_new);
      par0 ^= 1;
      grid_sync();
    }

    // ---- layer 1, depth 0..3 (d0 fuses w_in[1] @ layer-0 state) ----
#pragma unroll 1
    for (int d = 0; d < 4; ++d) {
      int m = 5 + d;
      float acc[4][8];
#pragma unroll
      for (int a = 0; a < 4; ++a)
#pragma unroll
        for (int c = 0; c < 8; ++c) acc[a][c] = 0.f;

      kpass(acc, g_state[1][par1], ws + m * 4096, ks, bg);
      if (d == 0)
        kpass(acc, g_state[0][par0], ws + 4 * 4096, ks, bg);

#pragma unroll
      for (int a = 0; a < 4; ++a) {
        *(float4*)(myred + a * 8) =
            make_float4(acc[a][0], acc[a][1], acc[a][2], acc[a][3]);
        *(float4*)(myred + a * 8 + 4) =
            make_float4(acc[a][4], acc[a][5], acc[a][6], acc[a][7]);
      }
      __syncthreads();

      float hs = bs[m * 8 + p];
      float gs = bs[m * 8 + 4 + p];
#pragma unroll
      for (int k2 = 0; k2 < 16; ++k2) {
        const float* rr = red + (k2 * 16 + (bq >> 2)) * 36 + (bq & 3) * 8;
        hs += rr[p];
        gs += rr[4 + p];
      }
      float s_old = __ldcg(g_state[1][par1] + gcol * 64 + bq);
      float hh = tanhf(hs);
      float gg = 1.f / (1.f + __expf(-gs));
      float s_new = fmaf(gg, hh - s_old, s_old);
      __stcg(g_state[1][par1 ^ 1] + gcol * 64 + bq, s_new);
      par1 ^= 1;
      if (d == 3)
        g_hidden[((size_t)t * Bn + bq) * 512 + gcol] = s_new;
      grid_sync();
    }
  }

  // ---- s_final: [L][B][H] appended after the logits block ----
  const size_t SFIN = (size_t)Tn * Bn * Vn;
  d_out[SFIN + 0 * (Bn * Hn) + bq * 512 + gcol] =
      __ldcg(g_state[0][par0] + gcol * 64 + bq);
  d_out[SFIN + 1 * (Bn * Hn) + bq * 512 + gcol] =
      __ldcg(g_state[1][par1] + gcol * 64 + bq);
}

// ---------------- kernel 3: logits = hidden @ w_fc + b_fc ----------------
__global__ void __launch_bounds__(NTHR, 1) logits_kernel(
    const float* __restrict__ w_fc, const float* __restrict__ b_fc,
    float* __restrict__ out)
{
  extern __shared__ float a_sm[];  // [64][512]
  int tid = threadIdx.x;
  size_t row0 = (size_t)blockIdx.x * 64;
  for (int i = tid; i < 64 * 512 / 4; i += NTHR)
    ((float4*)a_sm)[i] = ((const float4*)(g_hidden + row0 * 512))[i];
  __syncthreads();

  float acc[64];
#pragma unroll
  for (int r = 0; r < 64; ++r) acc[r] = 0.f;

#pragma unroll 2
  for (int k = 0; k < 512; k += 4) {
    float w0 = w_fc[(size_t)(k + 0) * 256 + tid];
    float w1 = w_fc[(size_t)(k + 1) * 256 + tid];
    float w2 = w_fc[(size_t)(k + 2) * 256 + tid];
    float w3 = w_fc[(size_t)(k + 3) * 256 + tid];
#pragma unroll
    for (int r = 0; r < 64; ++r) {
      float4 a = *(const float4*)(a_sm + r * 512 + k);
      acc[r] = fmaf(a.x, w0, acc[r]);
      acc[r] = fmaf(a.y, w1, acc[r]);
      acc[r] = fmaf(a.z, w2, acc[r]);
      acc[r] = fmaf(a.w, w3, acc[r]);
    }
  }
  float bias = b_fc[tid];
#pragma unroll
  for (int r = 0; r < 64; ++r)
    out[(row0 + r) * 256 + tid] = acc[r] + bias;
}

// ---------------- launch ----------------
extern "C" void kernel_launch(void* const* d_in, const int* in_sizes, int n_in,
                              void* d_out, int out_size) {
  const int*   x    = (const int*)d_in[0];    // [512,64] int32
  const float* emb  = (const float*)d_in[1];  // [256,512]
  const float* w_in = (const float*)d_in[2];  // [2,512,1024]
  const float* w_h  = (const float*)d_in[3];  // [2,4,512,1024]
  const float* b_h  = (const float*)d_in[4];  // [2,4,1024]
  const float* w_fc = (const float*)d_in[5];  // [512,256]
  const float* b_fc = (const float*)d_in[6];  // [256]
  float* out = (float*)d_out;

  const int SCAN_SMEM = (9 * 4096 + 72 + 256 * 36) * 4 + 64 * 4;
  const int LOGITS_SMEM = 64 * 512 * 4;
  cudaFuncSetAttribute(scan_kernel,
                       cudaFuncAttributeMaxDynamicSharedMemorySize, SCAN_SMEM);
  cudaFuncSetAttribute(logits_kernel,
                       cudaFuncAttributeMaxDynamicSharedMemorySize, LOGITS_SMEM);

  embhg_kernel<<<Vn, NTHR>>>(emb, w_in);
  scan_kernel<<<GRID_SCAN, NTHR, SCAN_SMEM>>>(x, w_in, w_h, b_h, out);
  logits_kernel<<<(Tn * Bn) / 64, NTHR, LOGITS_SMEM>>>(w_fc, b_fc, out);
}

// round 6
// speedup vs baseline: 2.2885x; 1.1983x over previous
#include <cuda_runtime.h>

#define Tn 512
#define Bn 64
#define Vn 256
#define Hn 512
#define GRID_SCAN 128
#define NTHR 256

// ---------------- device scratch (no allocations allowed) ----------------
__device__ float g_embhg[Vn * 2 * Hn];                 // emb @ w_in[0] : [256][1024]
__device__ float g_state[2][2][Hn * Bn];               // [layer][parity][col*64 + b]
__device__ float g_hidden[(size_t)Tn * Bn * Hn];       // [t][b][col]
__device__ unsigned g_bar_count;
__device__ unsigned g_bar_gen;

// ---------------- grid-wide barrier (release/acquire, no full fences) ----
__device__ __forceinline__ void grid_sync() {
  __syncthreads();
  if (threadIdx.x == 0) {
    unsigned gen;
    asm volatile("ld.relaxed.gpu.global.u32 %0, [%1];"
                 : "=r"(gen) : "l"(&g_bar_gen) : "memory");
    unsigned prev;
    asm volatile("atom.add.acq_rel.gpu.global.u32 %0, [%1], %2;"
                 : "=r"(prev) : "l"(&g_bar_count), "r"(1u) : "memory");
    if (prev == GRID_SCAN - 1u) {
      asm volatile("st.relaxed.gpu.global.u32 [%0], %1;"
                   :: "l"(&g_bar_count), "r"(0u) : "memory");
      asm volatile("st.release.gpu.global.u32 [%0], %1;"
                   :: "l"(&g_bar_gen), "r"(gen + 1u) : "memory");
    } else {
      unsigned cur;
      do {
        asm volatile("ld.acquire.gpu.global.u32 %0, [%1];"
                     : "=r"(cur) : "l"(&g_bar_gen) : "memory");
      } while (cur == gen);
    }
  }
  __syncthreads();
}

// ---------------- packed f32x2 helpers ----------------
__device__ __forceinline__ unsigned long long pack2(float v) {
  unsigned long long r;
  unsigned u = __float_as_uint(v);
  asm("mov.b64 %0, {%1, %1};" : "=l"(r) : "r"(u));
  return r;
}
__device__ __forceinline__ void fma2(unsigned long long& d,
                                     unsigned long long a,
                                     unsigned long long b) {
  asm("fma.rn.f32x2 %0, %1, %2, %0;" : "+l"(d) : "l"(a), "l"(b));
}

// one s scalar against 8 cols (4 packed FMA2)
#define FMA2ROW(bi, sv)                                                      \
  {                                                                          \
    unsigned long long sd = pack2(sv);                                       \
    fma2(acc[bi][0], sd, wa.x);                                              \
    fma2(acc[bi][1], sd, wa.y);                                              \
    fma2(acc[bi][2], sd, wb.x);                                              \
    fma2(acc[bi][3], sd, wb.y);                                              \
  }

// ---------------- K=512 partial dual-GEMM pass (f32x2) ----------------
// Thread (ks, bg): acc[b'][c2] += s[k][4bg+b'] * w[k][2c2..2c2+1]
// over its 32 k values (k = ks + 16*i). s via coalesced LDG.128 from L2,
// weights via broadcast LDS.128 pairs from resident SMEM [k][8].
__device__ __forceinline__ void kpass2(unsigned long long acc[4][4],
    const float* __restrict__ src, const float* __restrict__ wmat,
    int ks, int bg)
{
  const float4* srcv = (const float4*)src;   // [512][16] float4
  float4 sb[2][8];
#pragma unroll
  for (int j = 0; j < 8; ++j)
    sb[0][j] = __ldcg(srcv + (ks + 16 * j) * 16 + bg);
#pragma unroll
  for (int g = 0; g < 4; ++g) {
    if (g < 3) {
#pragma unroll
      for (int j = 0; j < 8; ++j)
        sb[(g + 1) & 1][j] =
            __ldcg(srcv + (ks + 16 * (8 * (g + 1) + j)) * 16 + bg);
    }
#pragma unroll
    for (int j = 0; j < 8; ++j) {
      int k = ks + 16 * (8 * g + j);
      const ulonglong2* wr = (const ulonglong2*)(wmat + k * 8);
      ulonglong2 wa = wr[0];     // cols (0,1),(2,3)
      ulonglong2 wb = wr[1];     // cols (4,5),(6,7)
      float4 s4 = sb[g & 1][j];
      FMA2ROW(0, s4.x)
      FMA2ROW(1, s4.y)
      FMA2ROW(2, s4.z)
      FMA2ROW(3, s4.w)
    }
  }
}

// ---------------- kernel 1: embhg = emb @ w_in[0] ----------------
__global__ void embhg_kernel(const float* __restrict__ emb,
                             const float* __restrict__ w_in) {
  __shared__ float e_sm[512];
  int v = blockIdx.x;
  for (int i = threadIdx.x; i < 512; i += NTHR) e_sm[i] = emb[v * 512 + i];
  __syncthreads();
  for (int j = threadIdx.x; j < 1024; j += NTHR) {
    float a0 = 0.f, a1 = 0.f, a2 = 0.f, a3 = 0.f;
    for (int k = 0; k < 512; k += 4) {
      a0 = fmaf(e_sm[k + 0], w_in[(size_t)(k + 0) * 1024 + j], a0);
      a1 = fmaf(e_sm[k + 1], w_in[(size_t)(k + 1) * 1024 + j], a1);
      a2 = fmaf(e_sm[k + 2], w_in[(size_t)(k + 2) * 1024 + j], a2);
      a3 = fmaf(e_sm[k + 3], w_in[(size_t)(k + 3) * 1024 + j], a3);
    }
    g_embhg[v * 1024 + j] = (a0 + a1) + (a2 + a3);
  }
}

// ---------------- kernel 2: persistent sequential scan ----------------
// SMEM: ws [9][512][8] weight rows ([h0..h3,g0..g3] per k), bs [9][8],
//       red [256][37] k-partial buffer (stride 37: 5 coprime 32 ->
//       conflict-free scalar STS and LDS in both store & combine patterns).
#define RSTRIDE 37
__global__ void __launch_bounds__(NTHR, 1) scan_kernel(
    const int* __restrict__ x, const float* __restrict__ w_in,
    const float* __restrict__ w_h, const float* __restrict__ b_h,
    float* __restrict__ d_out)
{
  extern __shared__ float smem[];
  float* ws = smem;                 // 9*4096 floats
  float* bs = ws + 9 * 4096;        // 72 floats
  float* red = bs + 72;             // 256*37 floats

  int tid = threadIdx.x;
  int cta = blockIdx.x;

  // --- weight slices -> SMEM, layout [m][k][8]: cols h0..h3,g0..g3 ---
  for (int idx = tid; idx < 9 * 4096; idx += NTHR) {
    int m = idx >> 12;
    int r = idx & 4095;
    int k = r >> 3;
    int c = r & 7;
    int col = cta * 4 + (c & 3) + ((c >> 2) << 9);
    const float* W = (m < 4)  ? (w_h + (size_t)m * 512 * 1024)
                   : (m == 4) ? (w_in + (size_t)512 * 1024)
                              : (w_h + (size_t)(m - 1) * 512 * 1024);
    ws[idx] = W[(size_t)k * 1024 + col];
  }
  if (tid < 72) {
    int m = tid >> 3, c = tid & 7;
    int col = cta * 4 + (c & 3) + ((c >> 2) << 9);
    float v = 0.f;
    if (m < 4)      v = b_h[m * 1024 + col];
    else if (m > 4) v = b_h[(m - 1) * 1024 + col];
    bs[tid] = v;
  }
  for (int i = cta * NTHR + tid; i < 2 * 2 * Hn * Bn; i += GRID_SCAN * NTHR)
    ((float*)g_state)[i] = 0.f;
  grid_sync();

  const int ks = tid >> 4;       // k-slice 0..15
  const int bg = tid & 15;       // batch group (4 batches)
  const int p  = tid >> 6;       // combine role: pair 0..3
  const int bq = tid & 63;       // combine role: batch 0..63
  const int bgq = bq >> 2;       // source batch-group
  const int jq  = bq & 3;        // within-group batch
  const int gcol = cta * 4 + p;  // global h-column of this pair
  float* myred = red + tid * RSTRIDE;
  int par0 = 0, par1 = 0;

#pragma unroll 1
  for (int t = 0; t < Tn; ++t) {
    // hoisted: token + embedding-projection operands (consumed at L0/d0)
    int tk = x[t * Bn + bq];
    float eh = g_embhg[tk * 1024 + gcol];
    float eg = g_embhg[tk * 1024 + 512 + gcol];

    // ---- layer 0, depth 0..3 ----
#pragma unroll 1
    for (int d = 0; d < 4; ++d) {
      const float* src = g_state[0][par0];
      float s_old = __ldcg(src + gcol * 64 + bq);   // early issue
      unsigned long long acc[4][4];
#pragma unroll
      for (int a = 0; a < 4; ++a)
#pragma unroll
        for (int c = 0; c < 4; ++c) acc[a][c] = 0ull;

      kpass2(acc, src, ws + d * 4096, ks, bg);

#pragma unroll
      for (int a = 0; a < 4; ++a)
#pragma unroll
        for (int c = 0; c < 4; ++c) {
          unsigned lo, hi;
          asm("mov.b64 {%0, %1}, %2;" : "=r"(lo), "=r"(hi) : "l"(acc[a][c]));
          myred[a * 8 + 2 * c] = __uint_as_float(lo);
          myred[a * 8 + 2 * c + 1] = __uint_as_float(hi);
        }
      __syncthreads();

      float h0 = bs[d * 8 + p], h1 = 0.f;
      float g0 = bs[d * 8 + 4 + p], g1 = 0.f;
#pragma unroll
      for (int k2 = 0; k2 < 16; k2 += 2) {
        const float* r0 = red + (k2 * 16 + bgq) * RSTRIDE + jq * 8;
        const float* r1 = red + ((k2 + 1) * 16 + bgq) * RSTRIDE + jq * 8;
        h0 += r0[p]; g0 += r0[4 + p];
        h1 += r1[p]; g1 += r1[4 + p];
      }
      float hs = h0 + h1, gs = g0 + g1;
      if (d == 0) { hs += eh; gs += eg; }
      float hh = tanhf(hs);
      float gg = 1.f / (1.f + __expf(-gs));
      float s_new = fmaf(gg, hh - s_old, s_old);
      __stcg(g_state[0][par0 ^ 1] + gcol * 64 + bq, s_new);
      par0 ^= 1;
      grid_sync();
    }

    // ---- layer 1, depth 0..3 (d0 fuses w_in[1] @ layer-0 state) ----
#pragma unroll 1
    for (int d = 0; d < 4; ++d) {
      int m = 5 + d;
      const float* src = g_state[1][par1];
      float s_old = __ldcg(src + gcol * 64 + bq);   // early issue
      unsigned long long acc[4][4];
#pragma unroll
      for (int a = 0; a < 4; ++a)
#pragma unroll
        for (int c = 0; c < 4; ++c) acc[a][c] = 0ull;

      kpass2(acc, src, ws + m * 4096, ks, bg);
      if (d == 0)
        kpass2(acc, g_state[0][par0], ws + 4 * 4096, ks, bg);

#pragma unroll
      for (int a = 0; a < 4; ++a)
#pragma unroll
        for (int c = 0; c < 4; ++c) {
          unsigned lo, hi;
          asm("mov.b64 {%0, %1}, %2;" : "=r"(lo), "=r"(hi) : "l"(acc[a][c]));
          myred[a * 8 + 2 * c] = __uint_as_float(lo);
          myred[a * 8 + 2 * c + 1] = __uint_as_float(hi);
        }
      __syncthreads();

      float h0 = bs[m * 8 + p], h1 = 0.f;
      float g0 = bs[m * 8 + 4 + p], g1 = 0.f;
#pragma unroll
      for (int k2 = 0; k2 < 16; k2 += 2) {
        const float* r0 = red + (k2 * 16 + bgq) * RSTRIDE + jq * 8;
        const float* r1 = red + ((k2 + 1) * 16 + bgq) * RSTRIDE + jq * 8;
        h0 += r0[p]; g0 += r0[4 + p];
        h1 += r1[p]; g1 += r1[4 + p];
      }
      float hs = h0 + h1, gs = g0 + g1;
      float hh = tanhf(hs);
      float gg = 1.f / (1.f + __expf(-gs));
      float s_new = fmaf(gg, hh - s_old, s_old);
      __stcg(g_state[1][par1 ^ 1] + gcol * 64 + bq, s_new);
      par1 ^= 1;
      if (d == 3)
        g_hidden[((size_t)t * Bn + bq) * 512 + gcol] = s_new;
      grid_sync();
    }
  }

  // ---- s_final: [L][B][H] appended after the logits block ----
  const size_t SFIN = (size_t)Tn * Bn * Vn;
  d_out[SFIN + 0 * (Bn * Hn) + bq * 512 + gcol] =
      __ldcg(g_state[0][par0] + gcol * 64 + bq);
  d_out[SFIN + 1 * (Bn * Hn) + bq * 512 + gcol] =
      __ldcg(g_state[1][par1] + gcol * 64 + bq);
}

// ---------------- kernel 3: logits = hidden @ w_fc + b_fc ----------------
__global__ void __launch_bounds__(NTHR, 1) logits_kernel(
    const float* __restrict__ w_fc, const float* __restrict__ b_fc,
    float* __restrict__ out)
{
  extern __shared__ float a_sm[];  // [64][512]
  int tid = threadIdx.x;
  size_t row0 = (size_t)blockIdx.x * 64;
  for (int i = tid; i < 64 * 512 / 4; i += NTHR)
    ((float4*)a_sm)[i] = ((const float4*)(g_hidden + row0 * 512))[i];
  __syncthreads();

  float acc[64];
#pragma unroll
  for (int r = 0; r < 64; ++r) acc[r] = 0.f;

#pragma unroll 2
  for (int k = 0; k < 512; k += 4) {
    float w0 = w_fc[(size_t)(k + 0) * 256 + tid];
    float w1 = w_fc[(size_t)(k + 1) * 256 + tid];
    float w2 = w_fc[(size_t)(k + 2) * 256 + tid];
    float w3 = w_fc[(size_t)(k + 3) * 256 + tid];
#pragma unroll
    for (int r = 0; r < 64; ++r) {
      float4 a = *(const float4*)(a_sm + r * 512 + k);
      acc[r] = fmaf(a.x, w0, acc[r]);
      acc[r] = fmaf(a.y, w1, acc[r]);
      acc[r] = fmaf(a.z, w2, acc[r]);
      acc[r] = fmaf(a.w, w3, acc[r]);
    }
  }
  float bias = b_fc[tid];
#pragma unroll
  for (int r = 0; r < 64; ++r)
    out[(row0 + r) * 256 + tid] = acc[r] + bias;
}

// ---------------- launch ----------------
extern "C" void kernel_launch(void* const* d_in, const int* in_sizes, int n_in,
                              void* d_out, int out_size) {
  const int*   x    = (const int*)d_in[0];    // [512,64] int32
  const float* emb  = (const float*)d_in[1];  // [256,512]
  const float* w_in = (const float*)d_in[2];  // [2,512,1024]
  const float* w_h  = (const float*)d_in[3];  // [2,4,512,1024]
  const float* b_h  = (const float*)d_in[4];  // [2,4,1024]
  const float* w_fc = (const float*)d_in[5];  // [512,256]
  const float* b_fc = (const float*)d_in[6];  // [256]
  float* out = (float*)d_out;

  const int SCAN_SMEM = (9 * 4096 + 72 + 256 * RSTRIDE) * 4;
  const int LOGITS_SMEM = 64 * 512 * 4;
  cudaFuncSetAttribute(scan_kernel,
                       cudaFuncAttributeMaxDynamicSharedMemorySize, SCAN_SMEM);
  cudaFuncSetAttribute(logits_kernel,
                       cudaFuncAttributeMaxDynamicSharedMemorySize, LOGITS_SMEM);

  embhg_kernel<<<Vn, NTHR>>>(emb, w_in);
  scan_kernel<<<GRID_SCAN, NTHR, SCAN_SMEM>>>(x, w_in, w_h, b_h, out);
  logits_kernel<<<(Tn * Bn) / 64, NTHR, LOGITS_SMEM>>>(w_fc, b_fc, out);
}

// round 10
// speedup vs baseline: 3.1827x; 1.3907x over previous
#include <cuda_runtime.h>

#define Tn 512
#define Bn 64
#define Vn 256
#define Hn 512
#define GRID_SCAN 128
#define NTHR 256
#define RSTRIDE 37

// ---------------- device scratch (no allocations allowed) ----------------
__device__ float g_embhg[Vn * 2 * Hn];             // emb @ w_in[0] : [256][1024]
__device__ float g_state[2][2][Hn * Bn];           // [layer][parity][col*64 + b]
__device__ float g_l0f[2][Hn * Bn];                // L0-final handoff, by t&1
__device__ float g_hidden[(size_t)Tn * Bn * Hn];   // [t][b][col]
__device__ unsigned g_bar_count;
__device__ unsigned g_bar_gen;

// ---------------- grid-wide barrier (release/acquire) ----------------
__device__ __forceinline__ void grid_sync() {
  __syncthreads();
  if (threadIdx.x == 0) {
    unsigned gen;
    asm volatile("ld.relaxed.gpu.global.u32 %0, [%1];"
                 : "=r"(gen) : "l"(&g_bar_gen) : "memory");
    unsigned prev;
    asm volatile("atom.add.acq_rel.gpu.global.u32 %0, [%1], %2;"
                 : "=r"(prev) : "l"(&g_bar_count), "r"(1u) : "memory");
    if (prev == GRID_SCAN - 1u) {
      asm volatile("st.relaxed.gpu.global.u32 [%0], %1;"
                   :: "l"(&g_bar_count), "r"(0u) : "memory");
      asm volatile("st.release.gpu.global.u32 [%0], %1;"
                   :: "l"(&g_bar_gen), "r"(gen + 1u) : "memory");
    } else {
      unsigned cur;
      do {
        asm volatile("ld.acquire.gpu.global.u32 %0, [%1];"
                     : "=r"(cur) : "l"(&g_bar_gen) : "memory");
      } while (cur == gen);
    }
  }
  __syncthreads();
}

// ---------------- packed f32x2 helpers ----------------
__device__ __forceinline__ unsigned long long pack2(float v) {
  unsigned long long r;
  unsigned u = __float_as_uint(v);
  asm("mov.b64 %0, {%1, %1};" : "=l"(r) : "r"(u));
  return r;
}
__device__ __forceinline__ void fma2(unsigned long long& d,
                                     unsigned long long a,
                                     unsigned long long b) {
  asm("fma.rn.f32x2 %0, %1, %2, %0;" : "+l"(d) : "l"(a), "l"(b));
}

// one s scalar against 16 cols (8 packed FMA2)
#define FMA2ROW16(bi, sv)                                                    \
  {                                                                          \
    unsigned long long sd = pack2(sv);                                       \
    fma2(acc[bi][0], sd, w0.x); fma2(acc[bi][1], sd, w0.y);                  \
    fma2(acc[bi][2], sd, w1.x); fma2(acc[bi][3], sd, w1.y);                  \
    fma2(acc[bi][4], sd, w2.x); fma2(acc[bi][5], sd, w2.y);                  \
    fma2(acc[bi][6], sd, w3.x); fma2(acc[bi][7], sd, w3.y);                  \
  }

// ---------------- K=512 partial GEMM pass: 4 batches x 16 cols ----------
// Thread (ks, bg) accumulates over its 32 k values (k = ks + 16*i).
// s via coalesced LDG.128 from L2 (double-buffered, prefetched), weights via
// broadcast LDS.128 from resident SMEM rows [k][16] = [h0..h7, g0..g7].
__device__ __forceinline__ void kpass16(unsigned long long acc[4][8],
    const float* __restrict__ src, const float* __restrict__ wmat,
    int ks, int bg)
{
  const float4* srcv = (const float4*)src;   // [512][16] float4
  float4 sb[2][8];
#pragma unroll
  for (int j = 0; j < 8; ++j)
    sb[0][j] = __ldcg(srcv + (ks + 16 * j) * 16 + bg);
#pragma unroll
  for (int g = 0; g < 4; ++g) {
    if (g < 3) {
#pragma unroll
      for (int j = 0; j < 8; ++j)
        sb[(g + 1) & 1][j] =
            __ldcg(srcv + (ks + 16 * (8 * (g + 1) + j)) * 16 + bg);
    }
#pragma unroll
    for (int j = 0; j < 8; ++j) {
      int k = ks + 16 * (8 * g + j);
      const ulonglong2* wr = (const ulonglong2*)(wmat + k * 16);
      ulonglong2 w0 = wr[0], w1 = wr[1], w2 = wr[2], w3 = wr[3];
      float4 s4 = sb[g & 1][j];
      FMA2ROW16(0, s4.x)
      FMA2ROW16(1, s4.y)
      FMA2ROW16(2, s4.z)
      FMA2ROW16(3, s4.w)
    }
  }
}

// ---------------- kernel 1: embhg = emb @ w_in[0] ----------------
// 64 CTAs x 4 vocab rows; float4 weight reads; each CTA reads w_in once.
__global__ void __launch_bounds__(NTHR, 1) embhg_kernel(
    const float* __restrict__ emb, const float* __restrict__ w_in) {
  __shared__ float e_sm[4 * 512];
  int v0 = blockIdx.x * 4;
  for (int i = threadIdx.x; i < 4 * 512; i += NTHR)
    e_sm[i] = emb[v0 * 512 + i];
  __syncthreads();
  int j4 = threadIdx.x * 4;
  float4 acc[4];
#pragma unroll
  for (int v = 0; v < 4; ++v) acc[v] = make_float4(0.f, 0.f, 0.f, 0.f);
  for (int k = 0; k < 512; ++k) {
    float4 w = *(const float4*)(w_in + (size_t)k * 1024 + j4);
#pragma unroll
    for (int v = 0; v < 4; ++v) {
      float e = e_sm[v * 512 + k];
      acc[v].x = fmaf(e, w.x, acc[v].x);
      acc[v].y = fmaf(e, w.y, acc[v].y);
      acc[v].z = fmaf(e, w.z, acc[v].z);
      acc[v].w = fmaf(e, w.w, acc[v].w);
    }
  }
#pragma unroll
  for (int v = 0; v < 4; ++v)
    *(float4*)(g_embhg + (size_t)(v0 + v) * 1024 + j4) = acc[v];
}

// ---------------- kernel 2: layer-pipelined persistent scan ----------------
// CTAs 0..63  = layer 0, columns cta*8..+7, timestep t
// CTAs 64..127= layer 1, columns (cta-64)*8..+7, timestep t-1
// SMEM: ws [<=5][512][16] (cols h0..h7,g0..g7), bs [<=5][16],
//       red [256][37] (stride 37: conflict-free scalar STS/LDS both patterns)
__global__ void __launch_bounds__(NTHR, 1) scan_kernel(
    const int* __restrict__ x, const float* __restrict__ w_in,
    const float* __restrict__ w_h, const float* __restrict__ b_h,
    float* __restrict__ d_out)
{
  extern __shared__ float smem[];
  float* ws = smem;                  // up to 5*8192 floats
  float* bs = ws + 5 * 8192;         // 80 floats
  float* red = bs + 80;              // 256*37 floats

  const int tid = threadIdx.x;
  const int cta = blockIdx.x;
  const int group = cta >> 6;        // 0 = layer0, 1 = layer1
  const int cg = cta & 63;           // column-group within layer

  // --- weight slices -> SMEM, layout [m][k][16] ---
  const int nm = group ? 5 : 4;
  for (int idx = tid; idx < nm * 8192; idx += NTHR) {
    int m = idx >> 13;
    int r = idx & 8191;
    int k = r >> 4;
    int c = r & 15;
    int col = cg * 8 + (c & 7) + ((c >> 3) << 9);
    const float* W;
    if (group == 0)      W = w_h + (size_t)m * 512 * 1024;
    else if (m < 4)      W = w_h + (size_t)(4 + m) * 512 * 1024;
    else                 W = w_in + (size_t)512 * 1024;
    ws[idx] = W[(size_t)k * 1024 + col];
  }
  if (tid < 64) {
    int m = tid >> 4, c = tid & 15;
    int col = cg * 8 + (c & 7) + ((c >> 3) << 9);
    bs[tid] = b_h[(group * 4 + m) * 1024 + col];
  }
  for (int i = cta * NTHR + tid; i < 2 * 2 * Hn * Bn; i += GRID_SCAN * NTHR)
    ((float*)g_state)[i] = 0.f;
  grid_sync();

  const int ks = tid >> 4;          // k-slice 0..15
  const int bg = tid & 15;          // batch group (4 batches)
  const int c0 = tid >> 6;          // combine role: column 0..3 (also c0+4)
  const int bq = tid & 63;          // combine role: batch 0..63
  const int redoff = (bq >> 2) * RSTRIDE + (bq & 3) * 8;
  const int colA = cg * 8 + c0;     // global h-columns handled in combine
  const int colB = colA + 4;
  float* myred = red + tid * RSTRIDE;
  float* mystate = (float*)g_state[group];
  int par = 0;

#pragma unroll 1
  for (int t = 0; t <= Tn; ++t) {
    const bool act = group == 0 ? (t < Tn) : (t >= 1);
    const int te = group == 0 ? t : t - 1;   // effective timestep

    // hoisted per-timestep operands (layer 0 d0 input projection)
    float ehA = 0.f, ehB = 0.f, egA = 0.f, egB = 0.f;
    if (group == 0 && act) {
      int tk = x[t * Bn + bq];
      ehA = g_embhg[tk * 1024 + colA];
      ehB = g_embhg[tk * 1024 + colB];
      egA = g_embhg[tk * 1024 + 512 + colA];
      egB = g_embhg[tk * 1024 + 512 + colB];
    }

#pragma unroll 1
    for (int d = 0; d < 4; ++d) {
      if (act) {
        const float* src = mystate + par * (Hn * Bn);
        float sA = __ldcg(src + colA * 64 + bq);   // early issue
        float sB = __ldcg(src + colB * 64 + bq);

        unsigned long long acc[4][8];
#pragma unroll
        for (int a = 0; a < 4; ++a)
#pragma unroll
          for (int c = 0; c < 8; ++c) acc[a][c] = 0ull;

        kpass16(acc, src, ws + d * 8192, ks, bg);
        if (group == 1 && d == 0)
          kpass16(acc, g_l0f[te & 1], ws + 4 * 8192, ks, bg);

        // ---- combine, phase H ----
#pragma unroll
        for (int a = 0; a < 4; ++a)
#pragma unroll
          for (int c = 0; c < 4; ++c) {
            unsigned lo, hi;
            asm("mov.b64 {%0, %1}, %2;" : "=r"(lo), "=r"(hi) : "l"(acc[a][c]));
            myred[a * 8 + 2 * c] = __uint_as_float(lo);
            myred[a * 8 + 2 * c + 1] = __uint_as_float(hi);
          }
        __syncthreads();
        float hsA = bs[d * 16 + c0];
        float hsB = bs[d * 16 + c0 + 4];
#pragma unroll
        for (int k2 = 0; k2 < 16; ++k2) {
          const float* rr = red + k2 * 16 * RSTRIDE + redoff;
          hsA += rr[c0];
          hsB += rr[c0 + 4];
        }
        __syncthreads();

        // ---- combine, phase G ----
#pragma unroll
        for (int a = 0; a < 4; ++a)
#pragma unroll
          for (int c = 0; c < 4; ++c) {
            unsigned lo, hi;
            asm("mov.b64 {%0, %1}, %2;" : "=r"(lo), "=r"(hi) : "l"(acc[a][4 + c]));
            myred[a * 8 + 2 * c] = __uint_as_float(lo);
            myred[a * 8 + 2 * c + 1] = __uint_as_float(hi);
          }
        __syncthreads();
        float gsA = bs[d * 16 + 8 + c0];
        float gsB = bs[d * 16 + 12 + c0];
#pragma unroll
        for (int k2 = 0; k2 < 16; ++k2) {
          const float* rr = red + k2 * 16 * RSTRIDE + redoff;
          gsA += rr[c0];
          gsB += rr[c0 + 4];
        }
        if (group == 0 && d == 0) {
          hsA += ehA; hsB += ehB; gsA += egA; gsB += egB;
        }
        float hhA = tanhf(hsA), hhB = tanhf(hsB);
        float ggA = 1.f / (1.f + __expf(-gsA));
        float ggB = 1.f / (1.f + __expf(-gsB));
        float snA = fmaf(ggA, hhA - sA, sA);
        float snB = fmaf(ggB, hhB - sB, sB);
        float* dst = mystate + (par ^ 1) * (Hn * Bn);
        __stcg(dst + colA * 64 + bq, snA);
        __stcg(dst + colB * 64 + bq, snB);
        if (d == 3) {
          if (group == 0) {
            __stcg(g_l0f[t & 1] + colA * 64 + bq, snA);
            __stcg(g_l0f[t & 1] + colB * 64 + bq, snB);
          } else {
            g_hidden[((size_t)te * Bn + bq) * 512 + colA] = snA;
            g_hidden[((size_t)te * Bn + bq) * 512 + colB] = snB;
          }
        }
        par ^= 1;
      }
      grid_sync();
    }
  }

  // ---- s_final: [L][B][H] appended after the logits block ----
  const size_t SFIN = (size_t)Tn * Bn * Vn;
  const float* fin = mystate + par * (Hn * Bn);
  d_out[SFIN + (size_t)group * (Bn * Hn) + bq * 512 + colA] =
      __ldcg(fin + colA * 64 + bq);
  d_out[SFIN + (size_t)group * (Bn * Hn) + bq * 512 + colB] =
      __ldcg(fin + colB * 64 + bq);
}

// ---------------- kernel 3: logits = hidden @ w_fc + b_fc ----------------
__global__ void __launch_bounds__(NTHR, 1) logits_kernel(
    const float* __restrict__ w_fc, const float* __restrict__ b_fc,
    float* __restrict__ out)
{
  extern __shared__ float a_sm[];  // [64][512]
  int tid = threadIdx.x;
  size_t row0 = (size_t)blockIdx.x * 64;
  for (int i = tid; i < 64 * 512 / 4; i += NTHR)
    ((float4*)a_sm)[i] = ((const float4*)(g_hidden + row0 * 512))[i];
  __syncthreads();

  float acc[64];
#pragma unroll
  for (int r = 0; r < 64; ++r) acc[r] = 0.f;

#pragma unroll 2
  for (int k = 0; k < 512; k += 4) {
    float w0 = w_fc[(size_t)(k + 0) * 256 + tid];
    float w1 = w_fc[(size_t)(k + 1) * 256 + tid];
    float w2 = w_fc[(size_t)(k + 2) * 256 + tid];
    float w3 = w_fc[(size_t)(k + 3) * 256 + tid];
#pragma unroll
    for (int r = 0; r < 64; ++r) {
      float4 a = *(const float4*)(a_sm + r * 512 + k);
      acc[r] = fmaf(a.x, w0, acc[r]);
      acc[r] = fmaf(a.y, w1, acc[r]);
      acc[r] = fmaf(a.z, w2, acc[r]);
      acc[r] = fmaf(a.w, w3, acc[r]);
    }
  }
  float bias = b_fc[tid];
#pragma unroll
  for (int r = 0; r < 64; ++r)
    out[(row0 + r) * 256 + tid] = acc[r] + bias;
}

// ---------------- launch ----------------
extern "C" void kernel_launch(void* const* d_in, const int* in_sizes, int n_in,
                              void* d_out, int out_size) {
  const int*   x    = (const int*)d_in[0];    // [512,64] int32
  const float* emb  = (const float*)d_in[1];  // [256,512]
  const float* w_in = (const float*)d_in[2];  // [2,512,1024]
  const float* w_h  = (const float*)d_in[3];  // [2,4,512,1024]
  const float* b_h  = (const float*)d_in[4];  // [2,4,1024]
  const float* w_fc = (const float*)d_in[5];  // [512,256]
  const float* b_fc = (const float*)d_in[6];  // [256]
  float* out = (float*)d_out;

  const int SCAN_SMEM = (5 * 8192 + 80 + 256 * RSTRIDE) * 4;
  const int LOGITS_SMEM = 64 * 512 * 4;
  cudaFuncSetAttribute(scan_kernel,
                       cudaFuncAttributeMaxDynamicSharedMemorySize, SCAN_SMEM);
  cudaFuncSetAttribute(logits_kernel,
                       cudaFuncAttributeMaxDynamicSharedMemorySize, LOGITS_SMEM);

  embhg_kernel<<<64, NTHR>>>(emb, w_in);
  scan_kernel<<<GRID_SCAN, NTHR, SCAN_SMEM>>>(x, w_in, w_h, b_h, out);
  logits_kernel<<<(Tn * Bn) / 64, NTHR, LOGITS_SMEM>>>(w_fc, b_fc, out);
}